// round 2
// baseline (speedup 1.0000x reference)
#include <cuda_runtime.h>
#include <stdint.h>

// XFlatRGBExtractorOp — masked channel select + stack.
// B=16, H=W=1536. Output (B,3,H,W) f32.
//   ch0 = r_mask ? xtrans[:,0] : chroma_pred[:,0]
//   ch1 = green_pred[:,0]
//   ch2 = b_mask ? xtrans[:,2] : chroma_pred[:,1]
// Masks are 6x6 tiled patterns.

#define Bsz 16
#define H 1536
#define W 1536
#define P (H * W)          // floats per plane
#define P4 (P / 4)         // float4 per plane (589824)
#define W4 (W / 4)         // float4 per row (384)
#define HHALF (H / 2)      // 768 ; 768 % 6 == 0 -> rows h and h+768 share mask phase

// 6-bit row masks: bit c set => take xtrans at column (w % 6) == c.
// R_POS rows: 0:{4} 1:{0,2} 2:{4} 3:{1} 4:{3,5} 5:{1}
// B_POS rows: 0:{1} 1:{3,5} 2:{1} 3:{4} 4:{0,2} 5:{4}
__constant__ unsigned c_rmask[6] = {0x10u, 0x05u, 0x10u, 0x02u, 0x28u, 0x02u};
__constant__ unsigned c_bmask[6] = {0x02u, 0x28u, 0x02u, 0x10u, 0x05u, 0x10u};

__global__ __launch_bounds__(W4) void xflat_rgb_kernel(
    const float4* __restrict__ green,   // B * P4
    const float4* __restrict__ xtrans,  // B * 3 * P4
    const float4* __restrict__ chroma,  // B * 2 * P4
    float4* __restrict__ out)           // B * 3 * P4
{
    const int t = threadIdx.x;                  // float4 column, 0..383
    const int h = blockIdx.x;                   // row in [0, 768)
    const int plane = blockIdx.y;               // 0..47
    const int b = plane / 3;
    const int c = plane - 3 * b;

    const size_t i0 = (size_t)h * W4 + t;
    const size_t i1 = i0 + (size_t)HHALF * W4;  // row h+768, same 6-row phase
    float4* const o = out + (size_t)plane * P4;

    if (c == 1) {
        // green: straight streaming copy of two rows
        const float4* const g = green + (size_t)b * P4;
        float4 a0 = __ldcs(g + i0);
        float4 a1 = __ldcs(g + i1);
        __stcs(o + i0, a0);
        __stcs(o + i1, a1);
        return;
    }

    // block-uniform row phase, per-thread column phase
    const int r  = h % 6;
    const int w6 = (t * 4) % 6;                 // 0, 2, or 4
    const unsigned rowm = (c == 0) ? c_rmask[r] : c_bmask[r];
    const unsigned sel  = (rowm >> w6) | (rowm << (6 - w6));

    const float4* const xp = xtrans + ((size_t)b * 3 + (c == 0 ? 0 : 2)) * P4;
    const float4* const pp = chroma + ((size_t)b * 2 + (c == 0 ? 0 : 1)) * P4;

    // front-batched independent loads (MLP = 4)
    float4 a0 = __ldcs(xp + i0);
    float4 a1 = __ldcs(xp + i1);
    float4 p0 = __ldcs(pp + i0);
    float4 p1 = __ldcs(pp + i1);

    float4 o0, o1;
    o0.x = (sel & 1u) ? a0.x : p0.x;
    o0.y = (sel & 2u) ? a0.y : p0.y;
    o0.z = (sel & 4u) ? a0.z : p0.z;
    o0.w = (sel & 8u) ? a0.w : p0.w;
    o1.x = (sel & 1u) ? a1.x : p1.x;
    o1.y = (sel & 2u) ? a1.y : p1.y;
    o1.z = (sel & 4u) ? a1.z : p1.z;
    o1.w = (sel & 8u) ? a1.w : p1.w;

    __stcs(o + i0, o0);
    __stcs(o + i1, o1);
}

extern "C" void kernel_launch(void* const* d_in, const int* in_sizes, int n_in,
                              void* d_out, int out_size)
{
    const float4* green  = (const float4*)d_in[0];  // (B,1,H,W)
    const float4* xtrans = (const float4*)d_in[1];  // (B,3,H,W)
    const float4* chroma = (const float4*)d_in[2];  // (B,2,H,W)
    float4* out = (float4*)d_out;                   // (B,3,H,W)

    dim3 grid(HHALF, Bsz * 3, 1);                   // 768 x 48 blocks, 384 thr
    xflat_rgb_kernel<<<grid, W4>>>(green, xtrans, chroma, out);
}

// round 3
// speedup vs baseline: 1.0139x; 1.0139x over previous
#include <cuda_runtime.h>
#include <stdint.h>

// XFlatRGBExtractorOp — masked channel select + stack.
// B=16, H=W=1536. Output (B,3,H,W) f32.
//   ch0 = r_mask ? xtrans[:,0] : chroma_pred[:,0]
//   ch1 = green_pred[:,0]
//   ch2 = b_mask ? xtrans[:,2] : chroma_pred[:,1]
// Masks are 6x6 tiled patterns. Pure streaming: traffic floor 1.208 GB.

#define Bsz 16
#define H 1536
#define W 1536
#define P (H * W)          // 2359296 floats per plane
#define P4 (P / 4)         // 589824 float4 per plane
#define W4 (W / 4)         // 384 float4 per row

// 6-bit row masks: bit c set => take xtrans at column (w % 6) == c.
// R_POS rows: 0:{4} 1:{0,2} 2:{4} 3:{1} 4:{3,5} 5:{1}
// B_POS rows: 0:{1} 1:{3,5} 2:{1} 3:{4} 4:{0,2} 5:{4}
__constant__ unsigned c_rmask[6] = {0x10u, 0x05u, 0x10u, 0x02u, 0x28u, 0x02u};
__constant__ unsigned c_bmask[6] = {0x02u, 0x28u, 0x02u, 0x10u, 0x05u, 0x10u};

__global__ __launch_bounds__(256) void xflat_rgb_kernel(
    const float4* __restrict__ green,   // B * P4
    const float4* __restrict__ xtrans,  // B * 3 * P4
    const float4* __restrict__ chroma,  // B * 2 * P4
    float4* __restrict__ out)           // B * 3 * P4
{
    const int i = blockIdx.x * 256 + threadIdx.x;   // float4 index within plane
    if (i >= P4) return;
    const int plane = blockIdx.y;                   // 0..3B-1
    const int b = plane / 3;
    const int c = plane - 3 * b;

    const size_t oidx = (size_t)plane * P4 + i;

    if (c == 1) {
        // green copy (uniform branch across the whole plane's blocks)
        __stcs(out + oidx, __ldcs(green + (size_t)b * P4 + i));
        return;
    }

    // row / column phase within the 6x6 tile
    const int h  = i / W4;
    const int w4 = (i - h * W4) * 4;                // starting column of this float4
    const int r  = h % 6;
    const int w6 = w4 % 6;                          // 0, 2, or 4

    const unsigned rowm = (c == 0) ? c_rmask[r] : c_bmask[r];
    // rotate so that bit k = mask for lane k (columns w6..w6+3 with wrap at 6)
    const unsigned sel = (rowm >> w6) | (rowm << (6 - w6));

    const int xch = (c == 0) ? 0 : 2;               // xtrans channel
    const int pch = (c == 0) ? 0 : 1;               // chroma channel

    const float4 a = __ldcs(xtrans + ((size_t)b * 3 + xch) * P4 + i);
    const float4 p = __ldcs(chroma + ((size_t)b * 2 + pch) * P4 + i);

    float4 o;
    o.x = (sel & 1u) ? a.x : p.x;
    o.y = (sel & 2u) ? a.y : p.y;
    o.z = (sel & 4u) ? a.z : p.z;
    o.w = (sel & 8u) ? a.w : p.w;
    __stcs(out + oidx, o);
}

extern "C" void kernel_launch(void* const* d_in, const int* in_sizes, int n_in,
                              void* d_out, int out_size)
{
    const float4* green  = (const float4*)d_in[0];  // (B,1,H,W)
    const float4* xtrans = (const float4*)d_in[1];  // (B,3,H,W)
    const float4* chroma = (const float4*)d_in[2];  // (B,2,H,W)
    float4* out = (float4*)d_out;                   // (B,3,H,W)

    dim3 grid((P4 + 255) / 256, Bsz * 3, 1);
    xflat_rgb_kernel<<<grid, 256>>>(green, xtrans, chroma, out);
}